// round 8
// baseline (speedup 1.0000x reference)
#include <cuda_runtime.h>
#include <cstdint>

#define WIRE_DIM   32
#define NUM_WIRES  64
#define ROW_ELEMS  (NUM_WIRES * WIRE_DIM)   // 2048 floats per batch row
#define WPB        2                        // warps per block
#define ITERS      4                        // rows per warp (pipelined ring)
#define NTHREADS   (WPB * 32)
#define RPB        (WPB * ITERS)            // 8 rows per block

typedef unsigned long long u64;

// ---- packed f32x2 helpers ----
__device__ __forceinline__ u64 pack2f(float lo, float hi) {
    u64 r; asm("mov.b64 %0, {%1, %2};" : "=l"(r) : "f"(lo), "f"(hi)); return r;
}
__device__ __forceinline__ void ffma2(u64 &d, u64 a, u64 b) {
    asm("fma.rn.f32x2 %0, %1, %2, %0;" : "+l"(d) : "l"(a), "l"(b));
}
__device__ __forceinline__ float2 unpack2(u64 v) {
    float2 f; asm("mov.b64 {%0, %1}, %2;" : "=f"(f.x), "=f"(f.y) : "l"(v)); return f;
}

// ---- cp.async (LDGSTS) helpers ----
__device__ __forceinline__ void cp16(uint32_t dst_smem, const float* src) {
    asm volatile("cp.async.cg.shared.global [%0], [%1], 16;" :: "r"(dst_smem), "l"(src));
}
__device__ __forceinline__ void cp_commit() { asm volatile("cp.async.commit_group;"); }
template <int N> __device__ __forceinline__ void cp_wait() {
    asm volatile("cp.async.wait_group %0;" :: "n"(N));
}

// ---- weights in constant memory (uniform loads -> LDCU, off the MIO path) ----
struct CPack {
    u64   Wlow[160];    // pairs: Wlow[p*10+h]  = (W1[2p][h],    W1[2p+1][h]),    p=0..15 (rows 0..31)
    u64   Whigh[160];   // pairs: Whigh[p*10+h] = (W1[32+2p][h], W1[32+2p+1][h]), p=0..15 (rows 32..63)
    float b1[10];
    float W2[10];
    float b2;
    float pad[5];
};
__constant__ CPack cc;
__device__   CPack g_pack;     // scratch filled by prep kernel, memcpy'd to cc

__global__ void prep_kernel(const float* __restrict__ W1,
                            const float* __restrict__ b1,
                            const float* __restrict__ W2,
                            const float* __restrict__ b2)
{
    int i = threadIdx.x;
    if (i < 160) {
        int p = i / 10, h = i - 10 * p;
        g_pack.Wlow[i]  = pack2f(W1[(2 * p) * 10 + h],      W1[(2 * p + 1) * 10 + h]);
        g_pack.Whigh[i] = pack2f(W1[(32 + 2 * p) * 10 + h], W1[(32 + 2 * p + 1) * 10 + h]);
    } else if (i < 170) {
        int h = i - 160;
        g_pack.b1[h] = b1[h];
        g_pack.W2[h] = W2[h];
    } else if (i == 170) {
        g_pack.b2 = b2[0];
    }
}

__global__ __launch_bounds__(NTHREADS)
void trainer_kernel(const float* __restrict__ outputs,
                    const int* __restrict__ tests_i32,
                    float* __restrict__ out,
                    int B)
{
    __shared__ __align__(16) float sx[WPB][2][ROW_ELEMS];   // 32 KB: x ring only

    const int tid  = threadIdx.x;
    const int warp = tid >> 5;
    const int lane = tid & 31;

    // --- detect tests dtype (int64 pairs have zero high-words at odd slots) ---
    int hvv = tests_i32[2 * lane + 1];
    #pragma unroll
    for (int o = 16; o > 0; o >>= 1) hvv |= __shfl_xor_sync(0xffffffffu, hvv, o);
    const bool is_i64 = (hvv == 0);

    const int rbase = (blockIdx.x * WPB + warp) * ITERS;
    const uint32_t sbuf[2] = {
        (uint32_t)__cvta_generic_to_shared(&sx[warp][0][0]),
        (uint32_t)__cvta_generic_to_shared(&sx[warp][1][0])
    };

    // stage one row: coalesced 16B cp.async -> chunk-rotated smem scatter
    auto stage_row = [&](int r, uint32_t sb) {
        const float* src = outputs + (size_t)r * ROW_ELEMS;
        #pragma unroll
        for (int t = 0; t < 16; t++) {
            int f = t * 32 + lane;
            int w = f >> 3;
            int c = f & 7;
            int off = w * 32 + (((c + w) & 7) << 2);
            cp16(sb + (uint32_t)(off << 2), src + (f << 2));
        }
    };

    if (rbase < B) stage_row(rbase, sbuf[0]);
    cp_commit();

    const float b2v = cc.b2;

    #pragma unroll
    for (int i = 0; i < ITERS; i++) {
        const int r = rbase + i;

        if (i + 1 < ITERS) {
            if (r + 1 < B) stage_row(r + 1, sbuf[(i + 1) & 1]);
            cp_commit();
            cp_wait<1>();
        } else {
            cp_wait<0>();
        }
        __syncwarp();
        if (r >= B) break;

        const float* xr = sx[warp][i & 1];

        // --- test indices (warp-uniform) ---
        int person, loc;
        if (is_i64) { person = tests_i32[4 * r]; loc = tests_i32[4 * r + 2]; }
        else        { person = tests_i32[2 * r]; loc = tests_i32[2 * r + 1]; }
        person &= 63;

        // --- person contribution: lanes 0..9 own h, weights via LDC (lane-indexed) ---
        const int hh = (lane < 10) ? lane : 0;
        u64 pcacc = pack2f(cc.b1[hh], 0.f);
        const float* px = &xr[person * 32];
        #pragma unroll
        for (int c = 0; c < 8; c++) {
            ulonglong2 pv = *(const ulonglong2*)&px[(((c + person) & 7) << 2)];  // broadcast LDS
            ffma2(pcacc, pv.x, cc.Wlow[(2 * c) * 10 + hh]);
            ffma2(pcacc, pv.y, cc.Wlow[(2 * c + 1) * 10 + hh]);
        }
        float2 pcp2 = unpack2(pcacc);
        float pcv = pcp2.x + pcp2.y;

        // --- init accumulators: acc[h] = (pc[h], 0) for wires lane and lane+32 ---
        u64 accA[10], accB[10];
        #pragma unroll
        for (int h = 0; h < 10; h++) {
            u64 p = pack2f(__shfl_sync(0xffffffffu, pcv, h), 0.f);
            accA[h] = p; accB[h] = p;
        }

        // --- main MLP: x from smem (2 LDS.128/chunk), weights via uniform LDCU ---
        const int bA = lane * 32;
        const int bB = (lane + 32) * 32;

        #pragma unroll
        for (int c = 0; c < 8; c++) {
            const int rot = ((c + lane) & 7) << 2;
            ulonglong2 xa = *(const ulonglong2*)&xr[bA + rot];   // d-pairs 2c, 2c+1
            ulonglong2 xb = *(const ulonglong2*)&xr[bB + rot];

            #pragma unroll
            for (int pp = 0; pp < 2; pp++) {
                const u64* wb = &cc.Whigh[(2 * c + pp) * 10];    // uniform -> LDCU
                u64 xav = pp ? xa.y : xa.x;
                u64 xbv = pp ? xb.y : xb.x;
                #pragma unroll
                for (int j = 0; j < 10; j++) {
                    u64 w = wb[j];
                    ffma2(accA[j], xav, w);
                    ffma2(accB[j], xbv, w);
                }
            }
        }

        // --- relu + output layer -> two logits per lane ---
        float la = b2v, lb = b2v;
        #pragma unroll
        for (int h = 0; h < 10; h++) {
            float w2h = cc.W2[h];                                 // uniform -> LDCU
            float2 fa = unpack2(accA[h]);
            float2 fb = unpack2(accB[h]);
            la += fmaxf(fa.x + fa.y, 0.f) * w2h;
            lb += fmaxf(fb.x + fb.y, 0.f) * w2h;
        }

        // --- warp log-softmax over 64 logits, pick location ---
        float m = fmaxf(la, lb);
        #pragma unroll
        for (int o = 16; o > 0; o >>= 1)
            m = fmaxf(m, __shfl_xor_sync(0xffffffffu, m, o));
        float s = __expf(la - m) + __expf(lb - m);
        #pragma unroll
        for (int o = 16; o > 0; o >>= 1)
            s += __shfl_xor_sync(0xffffffffu, s, o);

        float cand = (loc >> 5) ? lb : la;       // wire w -> lane (w&31), slot (w>>5)
        cand = __shfl_sync(0xffffffffu, cand, loc & 31);

        if (lane == 0) out[r] = -(cand - m - __logf(s));
    }
}

extern "C" void kernel_launch(void* const* d_in, const int* in_sizes, int n_in,
                              void* d_out, int out_size)
{
    const float* outputs = (const float*)d_in[0];
    const int*   tests   = (const int*)d_in[1];
    const float* W1      = (const float*)d_in[2];
    const float* b1      = (const float*)d_in[3];
    const float* W2      = (const float*)d_in[4];
    const float* b2      = (const float*)d_in[5];
    float* out = (float*)d_out;
    int B = out_size;

    // 1) build paired weights in device scratch
    prep_kernel<<<1, 192>>>(W1, b1, W2, b2);

    // 2) scratch -> constant memory (D2D async copy: graph-capturable, no allocs)
    void* src_addr = nullptr;
    void* dst_addr = nullptr;
    cudaGetSymbolAddress(&src_addr, g_pack);
    cudaGetSymbolAddress(&dst_addr, cc);
    cudaMemcpyAsync(dst_addr, src_addr, sizeof(CPack), cudaMemcpyDeviceToDevice, 0);

    // 3) main kernel: grid sized for a single wave at 7 blocks/SM
    int blocks = (B + RPB - 1) / RPB;
    trainer_kernel<<<blocks, NTHREADS>>>(outputs, tests, out, B);
}

// round 9
// speedup vs baseline: 1.0794x; 1.0794x over previous
#include <cuda_runtime.h>
#include <cstdint>

#define WIRE_DIM   32
#define NUM_WIRES  64
#define ROW_ELEMS  (NUM_WIRES * WIRE_DIM)   // 2048 floats per batch row
#define WPB        2                        // warps per block
#define STAGES     3                        // ring depth: 2 rows always in flight
#define ITERS      7                        // rows per warp
#define NTHREADS   (WPB * 32)
#define RPB        (WPB * ITERS)            // 14 rows per block

typedef unsigned long long u64;

// ---- packed f32x2 helpers ----
__device__ __forceinline__ u64 pack2f(float lo, float hi) {
    u64 r; asm("mov.b64 %0, {%1, %2};" : "=l"(r) : "f"(lo), "f"(hi)); return r;
}
__device__ __forceinline__ void ffma2(u64 &d, u64 a, u64 b) {
    asm("fma.rn.f32x2 %0, %1, %2, %0;" : "+l"(d) : "l"(a), "l"(b));
}
__device__ __forceinline__ float2 unpack2(u64 v) {
    float2 f; asm("mov.b64 {%0, %1}, %2;" : "=f"(f.x), "=f"(f.y) : "l"(v)); return f;
}

// ---- cp.async with L2 evict_last hint (input fits in L2 across graph replays) ----
__device__ __forceinline__ u64 mk_policy() {
    u64 p; asm("createpolicy.fractional.L2::evict_last.b64 %0, 1.0;" : "=l"(p)); return p;
}
__device__ __forceinline__ void cp16(uint32_t dst_smem, const float* src, u64 pol) {
    asm volatile("cp.async.cg.shared.global.L2::cache_hint [%0], [%1], 16, %2;"
                 :: "r"(dst_smem), "l"(src), "l"(pol));
}
__device__ __forceinline__ void cp_commit() { asm volatile("cp.async.commit_group;"); }
template <int N> __device__ __forceinline__ void cp_wait() {
    asm volatile("cp.async.wait_group %0;" :: "n"(N));
}

// ---- weights in constant memory (uniform LDCU, off the MIO path) ----
struct CPack {
    u64   Wlow[160];    // (W1[2p][h], W1[2p+1][h])       p=0..15  (rows 0..31)
    u64   Whigh[160];   // (W1[32+2p][h], W1[32+2p+1][h]) p=0..15  (rows 32..63)
    float b1[10];
    float W2[10];
    float b2;
    float pad[5];
};
__constant__ CPack cc;
__device__   CPack g_pack;

__global__ void prep_kernel(const float* __restrict__ W1,
                            const float* __restrict__ b1,
                            const float* __restrict__ W2,
                            const float* __restrict__ b2)
{
    int i = threadIdx.x;
    if (i < 160) {
        int p = i / 10, h = i - 10 * p;
        g_pack.Wlow[i]  = pack2f(W1[(2 * p) * 10 + h],      W1[(2 * p + 1) * 10 + h]);
        g_pack.Whigh[i] = pack2f(W1[(32 + 2 * p) * 10 + h], W1[(32 + 2 * p + 1) * 10 + h]);
    } else if (i < 170) {
        int h = i - 160;
        g_pack.b1[h] = b1[h];
        g_pack.W2[h] = W2[h];
    } else if (i == 170) {
        g_pack.b2 = b2[0];
    }
}

__global__ __launch_bounds__(NTHREADS)
void trainer_kernel(const float* __restrict__ outputs,
                    const int* __restrict__ tests_i32,
                    float* __restrict__ out,
                    int B)
{
    // 2 warps x 3 stages x 8KB = 49152 B (static smem limit, exact)
    __shared__ __align__(16) float sx[WPB][STAGES][ROW_ELEMS];

    const int tid  = threadIdx.x;
    const int warp = tid >> 5;
    const int lane = tid & 31;

    // --- detect tests dtype (int64 pairs have zero high-words at odd slots) ---
    int hvv = tests_i32[2 * lane + 1];
    #pragma unroll
    for (int o = 16; o > 0; o >>= 1) hvv |= __shfl_xor_sync(0xffffffffu, hvv, o);
    const bool is_i64 = (hvv == 0);

    const int rbase = (blockIdx.x * WPB + warp) * ITERS;
    uint32_t sbuf[STAGES];
    #pragma unroll
    for (int s = 0; s < STAGES; s++)
        sbuf[s] = (uint32_t)__cvta_generic_to_shared(&sx[warp][s][0]);

    const u64 pol = mk_policy();

    // stage one row: coalesced 16B cp.async -> chunk-rotated smem scatter
    auto stage_row = [&](int r, uint32_t sb) {
        const float* src = outputs + (size_t)r * ROW_ELEMS;
        #pragma unroll
        for (int t = 0; t < 16; t++) {
            int f = t * 32 + lane;
            int w = f >> 3;
            int c = f & 7;
            int off = w * 32 + (((c + w) & 7) << 2);
            cp16(sb + (uint32_t)(off << 2), src + (f << 2), pol);
        }
    };

    // preload rows rbase, rbase+1 (one commit group each)
    if (rbase < B) stage_row(rbase, sbuf[0]);
    cp_commit();
    if (rbase + 1 < B) stage_row(rbase + 1, sbuf[1]);
    cp_commit();

    const float b2v = cc.b2;

    #pragma unroll
    for (int i = 0; i < ITERS; i++) {
        const int r = rbase + i;

        // one commit per iteration keeps group accounting exact (empty at tail)
        if (i + 2 < ITERS && r + 2 < B) stage_row(r + 2, sbuf[(i + 2) % STAGES]);
        cp_commit();
        cp_wait<2>();          // rows i+1, i+2 may remain in flight; row i is done
        __syncwarp();
        if (r >= B) break;

        const float* xr = sx[warp][i % STAGES];

        // --- test indices (warp-uniform) ---
        int person, loc;
        if (is_i64) { person = tests_i32[4 * r]; loc = tests_i32[4 * r + 2]; }
        else        { person = tests_i32[2 * r]; loc = tests_i32[2 * r + 1]; }
        person &= 63;

        // --- person contribution: lanes 0..9 own h (weights via lane-indexed LDC) ---
        const int hh = (lane < 10) ? lane : 0;
        u64 pcacc = pack2f(cc.b1[hh], 0.f);
        const float* px = &xr[person * 32];
        #pragma unroll
        for (int c = 0; c < 8; c++) {
            ulonglong2 pv = *(const ulonglong2*)&px[(((c + person) & 7) << 2)];
            ffma2(pcacc, pv.x, cc.Wlow[(2 * c) * 10 + hh]);
            ffma2(pcacc, pv.y, cc.Wlow[(2 * c + 1) * 10 + hh]);
        }
        float2 pcp2 = unpack2(pcacc);
        float pcv = pcp2.x + pcp2.y;

        // --- init accumulators: acc[h] = (pc[h], 0) for wires lane and lane+32 ---
        u64 accA[10], accB[10];
        #pragma unroll
        for (int h = 0; h < 10; h++) {
            u64 p = pack2f(__shfl_sync(0xffffffffu, pcv, h), 0.f);
            accA[h] = p; accB[h] = p;
        }

        // --- main MLP: x via LDS.128 (conflict-free), weights via uniform LDCU ---
        const int bA = lane * 32;
        const int bB = (lane + 32) * 32;

        #pragma unroll
        for (int c = 0; c < 8; c++) {
            const int rot = ((c + lane) & 7) << 2;
            ulonglong2 xa = *(const ulonglong2*)&xr[bA + rot];   // d-pairs 2c, 2c+1
            ulonglong2 xb = *(const ulonglong2*)&xr[bB + rot];

            #pragma unroll
            for (int pp = 0; pp < 2; pp++) {
                const u64* wb = &cc.Whigh[(2 * c + pp) * 10];    // uniform -> LDCU
                u64 xav = pp ? xa.y : xa.x;
                u64 xbv = pp ? xb.y : xb.x;
                #pragma unroll
                for (int j = 0; j < 10; j++) {
                    u64 w = wb[j];
                    ffma2(accA[j], xav, w);
                    ffma2(accB[j], xbv, w);
                }
            }
        }

        // --- relu + output layer -> two logits per lane ---
        float la = b2v, lb = b2v;
        #pragma unroll
        for (int h = 0; h < 10; h++) {
            float w2h = cc.W2[h];
            float2 fa = unpack2(accA[h]);
            float2 fb = unpack2(accB[h]);
            la += fmaxf(fa.x + fa.y, 0.f) * w2h;
            lb += fmaxf(fb.x + fb.y, 0.f) * w2h;
        }

        // --- warp log-softmax over 64 logits, pick location ---
        float m = fmaxf(la, lb);
        #pragma unroll
        for (int o = 16; o > 0; o >>= 1)
            m = fmaxf(m, __shfl_xor_sync(0xffffffffu, m, o));
        float s = __expf(la - m) + __expf(lb - m);
        #pragma unroll
        for (int o = 16; o > 0; o >>= 1)
            s += __shfl_xor_sync(0xffffffffu, s, o);

        float cand = (loc >> 5) ? lb : la;       // wire w -> lane (w&31), slot (w>>5)
        cand = __shfl_sync(0xffffffffu, cand, loc & 31);

        if (lane == 0) out[r] = -(cand - m - __logf(s));
    }
}

extern "C" void kernel_launch(void* const* d_in, const int* in_sizes, int n_in,
                              void* d_out, int out_size)
{
    const float* outputs = (const float*)d_in[0];
    const int*   tests   = (const int*)d_in[1];
    const float* W1      = (const float*)d_in[2];
    const float* b1      = (const float*)d_in[3];
    const float* W2      = (const float*)d_in[4];
    const float* b2      = (const float*)d_in[5];
    float* out = (float*)d_out;
    int B = out_size;

    prep_kernel<<<1, 192>>>(W1, b1, W2, b2);

    void* src_addr = nullptr;
    void* dst_addr = nullptr;
    cudaGetSymbolAddress(&src_addr, g_pack);
    cudaGetSymbolAddress(&dst_addr, cc);
    cudaMemcpyAsync(dst_addr, src_addr, sizeof(CPack), cudaMemcpyDeviceToDevice, 0);

    int blocks = (B + RPB - 1) / RPB;
    trainer_kernel<<<blocks, NTHREADS>>>(outputs, tests, out, B);
}